// round 6
// baseline (speedup 1.0000x reference)
#include <cuda_runtime.h>
#include <cuda_bf16.h>
#include <cstdint>

// ---------------------------------------------------------------------------
// Problem constants
// ---------------------------------------------------------------------------
#define N_NODES 100000
#define N_EDGES 1600000
#define D_NODE  128
#define D_EDGE  128
#define D_IN    256
#define HID     256
#define D_OUT   128

// ---------------------------------------------------------------------------
// Scratch (device globals; allocations are forbidden)
// ---------------------------------------------------------------------------
__device__ int g_cnt[N_NODES];
__device__ int g_off[N_NODES + 1];
__device__ int g_cursor[N_NODES];
__device__ int g_eid[N_EDGES];

// Weight blob in EXACT mma.sync A-fragment order, bf16 hi/lo terms:
//   b32 index = layerBase + ((kstep*NFT + ft)*2 + term)*128 + lane*4 + reg
#define WF_L2_B32 65536
#define WF_L3_B32 131072
#define WF_TOTAL_B32 163840
__device__ __align__(16) uint4 g_wfrag[WF_TOTAL_B32 / 4];

// ---------------------------------------------------------------------------
// SMEM map:
//   act_hi  [256 feat][72 bf16] stride 144 B   @ 0       (36864)
//   act_lo                                      @ 36864   (36864)
//   mean    [64 node][132 f32]  stride 528 B   @ 73728   (33792)
// L3 f32 transpose scratch (128 x 68 f32, stride 272 B) overlays act area.
// ---------------------------------------------------------------------------
#define ACT_HI_OFF 0
#define ACT_LO_OFF 36864
#define MEAN_OFF   73728
#define SMEM_BYTES 107520

// ---------------------------------------------------------------------------
// PTX helpers (arch-portable, valid at compute_103)
// ---------------------------------------------------------------------------
__device__ __forceinline__ uint32_t smem_to_u32(const void* p) {
    uint32_t a;
    asm("{ .reg .u64 t; cvta.to.shared.u64 t, %1; cvt.u32.u64 %0, t; }"
        : "=r"(a) : "l"(p));
    return a;
}

#define LDMX4T(r, addr) \
    asm volatile("ldmatrix.sync.aligned.m8n8.x4.trans.shared.b16 {%0,%1,%2,%3}, [%4];" \
        : "=r"((r)[0]), "=r"((r)[1]), "=r"((r)[2]), "=r"((r)[3]) : "r"(addr))

#define MMA_BF16(d, a, b0v, b1v) \
    asm volatile("mma.sync.aligned.m16n8k16.row.col.f32.bf16.bf16.f32 " \
        "{%0,%1,%2,%3},{%4,%5,%6,%7},{%8,%9},{%0,%1,%2,%3};" \
        : "+f"((d)[0]), "+f"((d)[1]), "+f"((d)[2]), "+f"((d)[3]) \
        : "r"((a)[0]), "r"((a)[1]), "r"((a)[2]), "r"((a)[3]), \
          "r"(b0v), "r"(b1v))

// fp32 pair -> packed bf16x2 hi + lo (a in low half)
__device__ __forceinline__ void split_pack(float a, float b,
                                           uint32_t& hi, uint32_t& lo) {
    __nv_bfloat16 ah = __float2bfloat16(a);
    __nv_bfloat16 bh = __float2bfloat16(b);
    __nv_bfloat16 al = __float2bfloat16(a - __bfloat162float(ah));
    __nv_bfloat16 bl = __float2bfloat16(b - __bfloat162float(bh));
    hi = ((uint32_t)__bfloat16_as_ushort(bh) << 16) | (uint32_t)__bfloat16_as_ushort(ah);
    lo = ((uint32_t)__bfloat16_as_ushort(bl) << 16) | (uint32_t)__bfloat16_as_ushort(al);
}

// ---------------------------------------------------------------------------
// Kernel: zero degree counters
// ---------------------------------------------------------------------------
__global__ void zero_cnt_kernel(int n) {
    int i = blockIdx.x * blockDim.x + threadIdx.x;
    if (i < n) g_cnt[i] = 0;
}

// ---------------------------------------------------------------------------
// Kernel: degree count
// ---------------------------------------------------------------------------
__global__ void count_kernel(const int* __restrict__ col, int n_edges) {
    int e = blockIdx.x * blockDim.x + threadIdx.x;
    if (e < n_edges) atomicAdd(&g_cnt[__ldg(col + e)], 1);
}

// ---------------------------------------------------------------------------
// Kernel: single-block exclusive prefix scan over degrees -> g_off, g_cursor
// ---------------------------------------------------------------------------
#define SCAN_T 1024
__global__ void prefix_kernel(int n) {
    __shared__ int wsum[SCAN_T / 32];
    int tid = threadIdx.x;
    int lane = tid & 31, w = tid >> 5;
    int chunk = (n + SCAN_T - 1) / SCAN_T;
    int lo = tid * chunk;
    int hi = min(lo + chunk, n);
    int local = 0;
    for (int i = lo; i < hi; i++) local += g_cnt[i];
    int v = local;
    #pragma unroll
    for (int d = 1; d < 32; d <<= 1) {
        int t = __shfl_up_sync(0xffffffffu, v, d);
        if (lane >= d) v += t;
    }
    if (lane == 31) wsum[w] = v;
    __syncthreads();
    if (w == 0) {
        int s = (lane < SCAN_T / 32) ? wsum[lane] : 0;
        #pragma unroll
        for (int d = 1; d < 32; d <<= 1) {
            int t = __shfl_up_sync(0xffffffffu, s, d);
            if (lane >= d) s += t;
        }
        if (lane < SCAN_T / 32) wsum[lane] = s;
    }
    __syncthreads();
    int run = (v - local) + (w ? wsum[w - 1] : 0);   // exclusive base for chunk
    for (int i = lo; i < hi; i++) {
        int c = g_cnt[i];
        g_off[i] = run;
        g_cursor[i] = run;
        run += c;
    }
    if (lo < n && hi == n) g_off[n] = run;
}

// ---------------------------------------------------------------------------
// Kernel: CSR bucket fill (int atomics only)
// ---------------------------------------------------------------------------
__global__ void fill_kernel(const int* __restrict__ col, int n_edges) {
    int e = blockIdx.x * blockDim.x + threadIdx.x;
    if (e < n_edges) {
        int dst = __ldg(col + e);
        int pos = atomicAdd(&g_cursor[dst], 1);
        g_eid[pos] = e;
    }
}

// ---------------------------------------------------------------------------
// Kernel: weight prep — bf16 hi/lo fragments in mma A-operand order
// ---------------------------------------------------------------------------
__global__ void prep_kernel(const float* __restrict__ W1,
                            const float* __restrict__ W2,
                            const float* __restrict__ W3) {
    int i = blockIdx.x * blockDim.x + threadIdx.x;
    if (i >= WF_TOTAL_B32) return;
    uint32_t* blob = (uint32_t*)g_wfrag;
    const float* W; int idx, Nl, NFT;
    if (i < WF_L2_B32)      { W = W1; idx = i;             Nl = 256; NFT = 16; }
    else if (i < WF_L3_B32) { W = W2; idx = i - WF_L2_B32; Nl = 256; NFT = 16; }
    else                    { W = W3; idx = i - WF_L3_B32; Nl = 128; NFT = 8;  }
    int reg   = idx & 3;
    int lane  = (idx >> 2) & 31;
    int term  = (idx >> 7) & 1;
    int ft    = (idx >> 8) % NFT;
    int kstep = (idx >> 8) / NFT;
    int r = lane >> 2, t = lane & 3;
    int m = ft * 16 + r + (reg & 1) * 8;
    int k = kstep * 16 + t * 2 + (reg >> 1) * 8;
    float w0 = __ldg(W + (size_t)k * Nl + m);
    float w1 = __ldg(W + (size_t)(k + 1) * Nl + m);
    uint32_t hi, lo;
    split_pack(w0, w1, hi, lo);
    blob[i] = term ? lo : hi;
}

// ---------------------------------------------------------------------------
// MLP compute chunk (unchanged from round 5)
// ---------------------------------------------------------------------------
template<int NT>
__device__ __forceinline__ void compute_chunk(
    float acc[2][8][4],
    const uint4* __restrict__ wf,
    int ftBase, int NFT, int kc,
    uint32_t actHi, uint32_t actLo, int lane)
{
    const uint32_t bK  = (uint32_t)(lane & 15);
    const uint32_t bMH = (uint32_t)((lane >> 4) * 8);
    #pragma unroll
    for (int ktl = 0; ktl < 4; ktl++) {
        const int kstep = kc * 4 + ktl;
        uint32_t ah[NT][4], al[NT][4];
        #pragma unroll
        for (int i = 0; i < NT; i++) {
            const uint4* p = wf + (size_t)((kstep * NFT + ftBase + i) * 2) * 32 + lane;
            uint4 h = __ldg(p);
            uint4 l = __ldg(p + 32);
            ah[i][0] = h.x; ah[i][1] = h.y; ah[i][2] = h.z; ah[i][3] = h.w;
            al[i][0] = l.x; al[i][1] = l.y; al[i][2] = l.z; al[i][3] = l.w;
        }
        const uint32_t kByte = (uint32_t)(kstep * 16 + (int)bK) * 144u;
        #pragma unroll
        for (int mt = 0; mt < 4; mt++) {
            const uint32_t mByte = (uint32_t)(mt * 16 + (int)bMH) * 2u;
            uint32_t bh[4], bl[4];
            LDMX4T(bh, actHi + kByte + mByte);
            LDMX4T(bl, actLo + kByte + mByte);
            #pragma unroll
            for (int i = 0; i < NT; i++) {
                #pragma unroll
                for (int h = 0; h < 2; h++) {
                    MMA_BF16(acc[i][mt * 2 + h], ah[i], bh[2 * h], bh[2 * h + 1]);
                    MMA_BF16(acc[i][mt * 2 + h], ah[i], bl[2 * h], bl[2 * h + 1]);
                    MMA_BF16(acc[i][mt * 2 + h], al[i], bh[2 * h], bh[2 * h + 1]);
                }
            }
        }
    }
}

// ---------------------------------------------------------------------------
// Fused kernel: gather-mean (CSR) + 3-layer MLP on tensor cores.
// CTA = 64 nodes, 256 threads, 2 CTAs/SM.
// ---------------------------------------------------------------------------
__global__ void __launch_bounds__(256, 2)
mlp_kernel(const float* __restrict__ x,
           const float4* __restrict__ edge4,     // edge_attr as float4 rows
           const float* __restrict__ b1,
           const float* __restrict__ b2,
           const float* __restrict__ b3,
           float* __restrict__ out, int n)
{
    extern __shared__ char sm[];
    const uint32_t sb    = smem_to_u32(sm);
    const uint32_t actHi = sb + ACT_HI_OFF;
    const uint32_t actLo = sb + ACT_LO_OFF;

    const int tid  = threadIdx.x;
    const int warp = tid >> 5;
    const int lane = tid & 31;
    const int g    = lane >> 2;
    const int t    = lane & 3;
    const int m0   = blockIdx.x * 64;

    // ---- gather phase: warp w sums edges for nodes w*8 .. w*8+7 -------------
    #pragma unroll 1
    for (int j = 0; j < 8; j++) {
        const int nl = warp * 8 + j;
        const int m  = m0 + nl;
        float4 accv = make_float4(0.f, 0.f, 0.f, 0.f);
        int deg = 0;
        if (m < n) {
            const int beg = __ldg(&g_off[m]);
            const int end = __ldg(&g_off[m + 1]);
            deg = end - beg;
            for (int base = beg; base < end; base += 32) {
                const int cnt = min(32, end - base);
                int eid_l = 0;
                if (base + lane < end) eid_l = __ldg(&g_eid[base + lane]);
                #pragma unroll 4
                for (int q = 0; q < cnt; q++) {
                    int eid = __shfl_sync(0xffffffffu, eid_l, q);
                    float4 v = __ldg(edge4 + (size_t)eid * 32 + lane);
                    accv.x += v.x; accv.y += v.y; accv.z += v.z; accv.w += v.w;
                }
            }
        }
        const float inv = 1.0f / fmaxf((float)deg, 1.0f);
        accv.x *= inv; accv.y *= inv; accv.z *= inv; accv.w *= inv;
        *(float4*)(sm + MEAN_OFF + (size_t)nl * 528 + (size_t)lane * 16) = accv;
    }
    __syncthreads();

    // ---- input fill: act[feat][node] = split(concat(x, mean)) --------------
    {
        int r = tid >> 2;           // local node 0..63
        int q = tid & 3;            // feature quarter
        int m = m0 + r;
        bool valid = (m < n);
        const float4* xr = (const float4*)(x + (size_t)(valid ? m : 0) * D_NODE);
        const float4* mr = (const float4*)(sm + MEAN_OFF + (size_t)r * 528);
        #pragma unroll
        for (int j = 0; j < 16; j++) {
            int fb = q * 64 + j * 4;
            float4 v = make_float4(0.f, 0.f, 0.f, 0.f);
            if (q < 2) {
                if (valid) v = __ldg(xr + q * 16 + j);
            } else {
                v = mr[(q - 2) * 16 + j];       // zero already if invalid
            }
            float vals[4] = {v.x, v.y, v.z, v.w};
            #pragma unroll
            for (int e = 0; e < 4; e++) {
                __nv_bfloat16 hi = __float2bfloat16(vals[e]);
                __nv_bfloat16 lo = __float2bfloat16(vals[e] - __bfloat162float(hi));
                size_t o = (size_t)(fb + e) * 144 + (size_t)r * 2;
                *(__nv_bfloat16*)(sm + ACT_HI_OFF + o) = hi;
                *(__nv_bfloat16*)(sm + ACT_LO_OFF + o) = lo;
            }
        }
    }
    __syncthreads();

    float acc[2][8][4];

    // ---- Layers 1 & 2 (K=256, N=256) ---------------------------------------
    #pragma unroll 1
    for (int L = 0; L < 2; L++) {
        const uint4* wf = g_wfrag + (L == 0 ? 0 : WF_L2_B32 / 4);
        #pragma unroll
        for (int i = 0; i < 2; i++)
            #pragma unroll
            for (int mt = 0; mt < 8; mt++)
                #pragma unroll
                for (int q = 0; q < 4; q++) acc[i][mt][q] = 0.f;

        #pragma unroll
        for (int kc = 0; kc < 4; kc++)
            compute_chunk<2>(acc, wf, warp * 2, 16, kc, actHi, actLo, lane);

        __syncthreads();

        const float* bias = (L == 0) ? b1 : b2;
        const int nb = warp * 32;
        #pragma unroll
        for (int i = 0; i < 2; i++) {
            int fb = nb + i * 16;
            float bg  = __ldg(bias + fb + g);
            float bg8 = __ldg(bias + fb + g + 8);
            size_t rowG  = (size_t)(fb + g) * 144;
            size_t rowG8 = (size_t)(fb + g + 8) * 144;
            #pragma unroll
            for (int mt = 0; mt < 8; mt++) {
                float v0 = fmaxf(acc[i][mt][0] + bg,  0.f);
                float v1 = fmaxf(acc[i][mt][1] + bg,  0.f);
                float v2 = fmaxf(acc[i][mt][2] + bg8, 0.f);
                float v3 = fmaxf(acc[i][mt][3] + bg8, 0.f);
                uint32_t h01, l01, h23, l23;
                split_pack(v0, v1, h01, l01);
                split_pack(v2, v3, h23, l23);
                size_t mB = (size_t)(mt * 8 + 2 * t) * 2;
                *(uint32_t*)(sm + ACT_HI_OFF + rowG  + mB) = h01;
                *(uint32_t*)(sm + ACT_LO_OFF + rowG  + mB) = l01;
                *(uint32_t*)(sm + ACT_HI_OFF + rowG8 + mB) = h23;
                *(uint32_t*)(sm + ACT_LO_OFF + rowG8 + mB) = l23;
            }
        }
        __syncthreads();
    }

    // ---- Layer 3 (K=256, N=128) ---------------------------------------------
    #pragma unroll
    for (int mt = 0; mt < 8; mt++)
        #pragma unroll
        for (int q = 0; q < 4; q++) acc[0][mt][q] = 0.f;

    #pragma unroll
    for (int kc = 0; kc < 4; kc++)
        compute_chunk<1>(acc, g_wfrag + WF_L3_B32 / 4, warp, 8, kc,
                         actHi, actLo, lane);

    // ---- final epilogue: bias, transpose via f32 scratch, coalesced store ---
    {
        const int nb = warp * 16;
        float bg  = __ldg(b3 + nb + g);
        float bg8 = __ldg(b3 + nb + g + 8);
        __syncthreads();
        #pragma unroll
        for (int mt = 0; mt < 8; mt++) {
            float2 v01 = make_float2(acc[0][mt][0] + bg,  acc[0][mt][1] + bg);
            float2 v23 = make_float2(acc[0][mt][2] + bg8, acc[0][mt][3] + bg8);
            size_t mB = (size_t)(mt * 8 + 2 * t) * 4;
            *(float2*)(sm + (size_t)(nb + g)     * 272 + mB) = v01;
            *(float2*)(sm + (size_t)(nb + g + 8) * 272 + mB) = v23;
        }
        __syncthreads();
        int mloc = tid >> 2, fgrp = tid & 3;
        int m = m0 + mloc;
        if (m < n) {
            const float* scr = (const float*)sm;
            #pragma unroll
            for (int i = 0; i < 8; i++) {
                int f = fgrp * 32 + i * 4;
                float4 v;
                v.x = scr[(f + 0) * 68 + mloc];
                v.y = scr[(f + 1) * 68 + mloc];
                v.z = scr[(f + 2) * 68 + mloc];
                v.w = scr[(f + 3) * 68 + mloc];
                *(float4*)(out + (size_t)m * D_OUT + f) = v;
            }
        }
    }
}

// ---------------------------------------------------------------------------
// kernel_launch
// Inputs: 0=x [N,128] f32, 1=edge_index [2,E] i32, 2=edge_attr [E,128] f32,
//         3=W1 [256,256], 4=b1, 5=W2 [256,256], 6=b2, 7=W3 [256,128], 8=b3.
// ---------------------------------------------------------------------------
extern "C" void kernel_launch(void* const* d_in, const int* in_sizes, int n_in,
                              void* d_out, int out_size) {
    const float* x  = (const float*)d_in[0];
    const int* ei   = (const int*)d_in[1];
    const float* ea = (const float*)d_in[2];
    const float* W1 = (const float*)d_in[3];
    const float* b1 = (const float*)d_in[4];
    const float* W2 = (const float*)d_in[5];
    const float* b2 = (const float*)d_in[6];
    const float* W3 = (const float*)d_in[7];
    const float* b3 = (const float*)d_in[8];
    float* out = (float*)d_out;

    const int n = in_sizes[0] / D_NODE;              // 100000
    const int n_edges = in_sizes[2] / D_EDGE;        // 1600000
    const int* col = ei + n_edges;                   // edge_index[1]

    // 1) CSR build
    zero_cnt_kernel<<<(n + 255) / 256, 256>>>(n);
    count_kernel<<<(n_edges + 255) / 256, 256>>>(col, n_edges);
    prefix_kernel<<<1, SCAN_T>>>(n);
    fill_kernel<<<(n_edges + 255) / 256, 256>>>(col, n_edges);
    // 2) weight prep (fragment-order split)
    prep_kernel<<<(WF_TOTAL_B32 + 255) / 256, 256>>>(W1, W2, W3);
    // 3) fused gather + tensor-core MLP
    {
        static int smem_set = 0;
        if (!smem_set) {
            cudaFuncSetAttribute(mlp_kernel,
                                 cudaFuncAttributeMaxDynamicSharedMemorySize,
                                 SMEM_BYTES);
            smem_set = 1;
        }
        int blocks = (n + 63) / 64;                  // 1563
        mlp_kernel<<<blocks, 256, SMEM_BYTES>>>(x, (const float4*)ea,
                                                b1, b2, b3, out, n);
    }
}

// round 7
// speedup vs baseline: 1.1397x; 1.1397x over previous
#include <cuda_runtime.h>
#include <cuda_bf16.h>
#include <cstdint>

// ---------------------------------------------------------------------------
// Problem constants
// ---------------------------------------------------------------------------
#define N_NODES 100000
#define N_EDGES 1600000
#define D_NODE  128
#define D_EDGE  128
#define D_IN    256
#define HID     256
#define D_OUT   128

// ---------------------------------------------------------------------------
// Scratch (device globals; allocations are forbidden)
// ---------------------------------------------------------------------------
__device__ int g_cnt[N_NODES];
__device__ int g_off[N_NODES + 1];
__device__ int g_cursor[N_NODES];
__device__ int g_eid[N_EDGES];
__device__ __align__(16) float g_mean[(size_t)N_NODES * D_EDGE];

// Weight blob in EXACT mma.sync A-fragment order, bf16 hi/lo terms:
//   b32 index = layerBase + ((kstep*NFT + ft)*2 + term)*128 + lane*4 + reg
#define WF_L2_B32 65536
#define WF_L3_B32 131072
#define WF_TOTAL_B32 163840
__device__ __align__(16) uint4 g_wfrag[WF_TOTAL_B32 / 4];

// ---------------------------------------------------------------------------
// SMEM map: activations only (hi + lo), [256 feat][72 bf16] stride 144 B.
// L3 f32 transpose scratch (128 x 68 f32, stride 272 B) overlays act area.
// ---------------------------------------------------------------------------
#define ACT_HI_OFF 0
#define ACT_LO_OFF 36864
#define SMEM_BYTES 73728

// ---------------------------------------------------------------------------
// PTX helpers (arch-portable, valid at compute_103)
// ---------------------------------------------------------------------------
__device__ __forceinline__ uint32_t smem_to_u32(const void* p) {
    uint32_t a;
    asm("{ .reg .u64 t; cvta.to.shared.u64 t, %1; cvt.u32.u64 %0, t; }"
        : "=r"(a) : "l"(p));
    return a;
}

#define LDMX4T(r, addr) \
    asm volatile("ldmatrix.sync.aligned.m8n8.x4.trans.shared.b16 {%0,%1,%2,%3}, [%4];" \
        : "=r"((r)[0]), "=r"((r)[1]), "=r"((r)[2]), "=r"((r)[3]) : "r"(addr))

#define MMA_BF16(d, a, b0v, b1v) \
    asm volatile("mma.sync.aligned.m16n8k16.row.col.f32.bf16.bf16.f32 " \
        "{%0,%1,%2,%3},{%4,%5,%6,%7},{%8,%9},{%0,%1,%2,%3};" \
        : "+f"((d)[0]), "+f"((d)[1]), "+f"((d)[2]), "+f"((d)[3]) \
        : "r"((a)[0]), "r"((a)[1]), "r"((a)[2]), "r"((a)[3]), \
          "r"(b0v), "r"(b1v))

// fp32 pair -> packed bf16x2 hi + lo (a in low half)
__device__ __forceinline__ void split_pack(float a, float b,
                                           uint32_t& hi, uint32_t& lo) {
    __nv_bfloat16 ah = __float2bfloat16(a);
    __nv_bfloat16 bh = __float2bfloat16(b);
    __nv_bfloat16 al = __float2bfloat16(a - __bfloat162float(ah));
    __nv_bfloat16 bl = __float2bfloat16(b - __bfloat162float(bh));
    hi = ((uint32_t)__bfloat16_as_ushort(bh) << 16) | (uint32_t)__bfloat16_as_ushort(ah);
    lo = ((uint32_t)__bfloat16_as_ushort(bl) << 16) | (uint32_t)__bfloat16_as_ushort(al);
}

// ---------------------------------------------------------------------------
// Kernel: zero degree counters
// ---------------------------------------------------------------------------
__global__ void zero_cnt_kernel(int n) {
    int i = blockIdx.x * blockDim.x + threadIdx.x;
    if (i < n) g_cnt[i] = 0;
}

// ---------------------------------------------------------------------------
// Kernel: degree count
// ---------------------------------------------------------------------------
__global__ void count_kernel(const int* __restrict__ col, int n_edges) {
    int e = blockIdx.x * blockDim.x + threadIdx.x;
    if (e < n_edges) atomicAdd(&g_cnt[__ldg(col + e)], 1);
}

// ---------------------------------------------------------------------------
// Kernel: single-block exclusive prefix scan over degrees -> g_off, g_cursor
// ---------------------------------------------------------------------------
#define SCAN_T 1024
__global__ void prefix_kernel(int n) {
    __shared__ int wsum[SCAN_T / 32];
    int tid = threadIdx.x;
    int lane = tid & 31, w = tid >> 5;
    int chunk = (n + SCAN_T - 1) / SCAN_T;
    int lo = tid * chunk;
    int hi = min(lo + chunk, n);
    int local = 0;
    for (int i = lo; i < hi; i++) local += g_cnt[i];
    int v = local;
    #pragma unroll
    for (int d = 1; d < 32; d <<= 1) {
        int t = __shfl_up_sync(0xffffffffu, v, d);
        if (lane >= d) v += t;
    }
    if (lane == 31) wsum[w] = v;
    __syncthreads();
    if (w == 0) {
        int s = (lane < SCAN_T / 32) ? wsum[lane] : 0;
        #pragma unroll
        for (int d = 1; d < 32; d <<= 1) {
            int t = __shfl_up_sync(0xffffffffu, s, d);
            if (lane >= d) s += t;
        }
        if (lane < SCAN_T / 32) wsum[lane] = s;
    }
    __syncthreads();
    int run = (v - local) + (w ? wsum[w - 1] : 0);   // exclusive base for chunk
    for (int i = lo; i < hi; i++) {
        int c = g_cnt[i];
        g_off[i] = run;
        g_cursor[i] = run;
        run += c;
    }
    if (lo < n && hi == n) g_off[n] = run;
}

// ---------------------------------------------------------------------------
// Kernel: CSR bucket fill (int atomics only)
// ---------------------------------------------------------------------------
__global__ void fill_kernel(const int* __restrict__ col, int n_edges) {
    int e = blockIdx.x * blockDim.x + threadIdx.x;
    if (e < n_edges) {
        int dst = __ldg(col + e);
        int pos = atomicAdd(&g_cursor[dst], 1);
        g_eid[pos] = e;
    }
}

// ---------------------------------------------------------------------------
// Kernel: gather-mean. One warp per node, 4 independent accumulators for MLP.
// High occupancy (tiny reg/smem footprint) -> saturates HBM read bandwidth.
// ---------------------------------------------------------------------------
__global__ void __launch_bounds__(256)
gather_kernel(const float4* __restrict__ edge4, int n) {
    int node = blockIdx.x * 8 + (threadIdx.x >> 5);
    int lane = threadIdx.x & 31;
    if (node >= n) return;
    const int beg = __ldg(&g_off[node]);
    const int end = __ldg(&g_off[node + 1]);
    float4 a0 = make_float4(0.f, 0.f, 0.f, 0.f);
    float4 a1 = make_float4(0.f, 0.f, 0.f, 0.f);
    float4 a2 = make_float4(0.f, 0.f, 0.f, 0.f);
    float4 a3 = make_float4(0.f, 0.f, 0.f, 0.f);
    for (int base = beg; base < end; base += 32) {
        const int cnt = min(32, end - base);
        int eid_l = 0;
        if (base + lane < end) eid_l = __ldg(&g_eid[base + lane]);
        int q = 0;
        for (; q + 4 <= cnt; q += 4) {
            int e0 = __shfl_sync(0xffffffffu, eid_l, q + 0);
            int e1 = __shfl_sync(0xffffffffu, eid_l, q + 1);
            int e2 = __shfl_sync(0xffffffffu, eid_l, q + 2);
            int e3 = __shfl_sync(0xffffffffu, eid_l, q + 3);
            float4 v0 = __ldg(edge4 + (size_t)e0 * 32 + lane);
            float4 v1 = __ldg(edge4 + (size_t)e1 * 32 + lane);
            float4 v2 = __ldg(edge4 + (size_t)e2 * 32 + lane);
            float4 v3 = __ldg(edge4 + (size_t)e3 * 32 + lane);
            a0.x += v0.x; a0.y += v0.y; a0.z += v0.z; a0.w += v0.w;
            a1.x += v1.x; a1.y += v1.y; a1.z += v1.z; a1.w += v1.w;
            a2.x += v2.x; a2.y += v2.y; a2.z += v2.z; a2.w += v2.w;
            a3.x += v3.x; a3.y += v3.y; a3.z += v3.z; a3.w += v3.w;
        }
        for (; q < cnt; q++) {
            int e0 = __shfl_sync(0xffffffffu, eid_l, q);
            float4 v0 = __ldg(edge4 + (size_t)e0 * 32 + lane);
            a0.x += v0.x; a0.y += v0.y; a0.z += v0.z; a0.w += v0.w;
        }
    }
    const float inv = 1.0f / fmaxf((float)(end - beg), 1.0f);
    float4 o;
    o.x = (a0.x + a1.x + a2.x + a3.x) * inv;
    o.y = (a0.y + a1.y + a2.y + a3.y) * inv;
    o.z = (a0.z + a1.z + a2.z + a3.z) * inv;
    o.w = (a0.w + a1.w + a2.w + a3.w) * inv;
    *(float4*)(g_mean + (size_t)node * D_EDGE + lane * 4) = o;
}

// ---------------------------------------------------------------------------
// Kernel: weight prep — bf16 hi/lo fragments in mma A-operand order
// ---------------------------------------------------------------------------
__global__ void prep_kernel(const float* __restrict__ W1,
                            const float* __restrict__ W2,
                            const float* __restrict__ W3) {
    int i = blockIdx.x * blockDim.x + threadIdx.x;
    if (i >= WF_TOTAL_B32) return;
    uint32_t* blob = (uint32_t*)g_wfrag;
    const float* W; int idx, Nl, NFT;
    if (i < WF_L2_B32)      { W = W1; idx = i;             Nl = 256; NFT = 16; }
    else if (i < WF_L3_B32) { W = W2; idx = i - WF_L2_B32; Nl = 256; NFT = 16; }
    else                    { W = W3; idx = i - WF_L3_B32; Nl = 128; NFT = 8;  }
    int reg   = idx & 3;
    int lane  = (idx >> 2) & 31;
    int term  = (idx >> 7) & 1;
    int ft    = (idx >> 8) % NFT;
    int kstep = (idx >> 8) / NFT;
    int r = lane >> 2, t = lane & 3;
    int m = ft * 16 + r + (reg & 1) * 8;
    int k = kstep * 16 + t * 2 + (reg >> 1) * 8;
    float w0 = __ldg(W + (size_t)k * Nl + m);
    float w1 = __ldg(W + (size_t)(k + 1) * Nl + m);
    uint32_t hi, lo;
    split_pack(w0, w1, hi, lo);
    blob[i] = term ? lo : hi;
}

// ---------------------------------------------------------------------------
// MLP compute chunk (A via LDG.128 fragments, B via ldmatrix.trans, 3-term)
// ---------------------------------------------------------------------------
template<int NT>
__device__ __forceinline__ void compute_chunk(
    float acc[2][8][4],
    const uint4* __restrict__ wf,
    int ftBase, int NFT, int kc,
    uint32_t actHi, uint32_t actLo, int lane)
{
    const uint32_t bK  = (uint32_t)(lane & 15);
    const uint32_t bMH = (uint32_t)((lane >> 4) * 8);
    #pragma unroll
    for (int ktl = 0; ktl < 4; ktl++) {
        const int kstep = kc * 4 + ktl;
        uint32_t ah[NT][4], al[NT][4];
        #pragma unroll
        for (int i = 0; i < NT; i++) {
            const uint4* p = wf + (size_t)((kstep * NFT + ftBase + i) * 2) * 32 + lane;
            uint4 h = __ldg(p);
            uint4 l = __ldg(p + 32);
            ah[i][0] = h.x; ah[i][1] = h.y; ah[i][2] = h.z; ah[i][3] = h.w;
            al[i][0] = l.x; al[i][1] = l.y; al[i][2] = l.z; al[i][3] = l.w;
        }
        const uint32_t kByte = (uint32_t)(kstep * 16 + (int)bK) * 144u;
        #pragma unroll
        for (int mt = 0; mt < 4; mt++) {
            const uint32_t mByte = (uint32_t)(mt * 16 + (int)bMH) * 2u;
            uint32_t bh[4], bl[4];
            LDMX4T(bh, actHi + kByte + mByte);
            LDMX4T(bl, actLo + kByte + mByte);
            #pragma unroll
            for (int i = 0; i < NT; i++) {
                #pragma unroll
                for (int h = 0; h < 2; h++) {
                    MMA_BF16(acc[i][mt * 2 + h], ah[i], bh[2 * h], bh[2 * h + 1]);
                    MMA_BF16(acc[i][mt * 2 + h], ah[i], bl[2 * h], bl[2 * h + 1]);
                    MMA_BF16(acc[i][mt * 2 + h], al[i], bh[2 * h], bh[2 * h + 1]);
                }
            }
        }
    }
}

// ---------------------------------------------------------------------------
// Kernel: fused 3-layer MLP. CTA = 64 nodes, 256 threads, 2 CTAs/SM.
// ---------------------------------------------------------------------------
__global__ void __launch_bounds__(256, 2)
mlp_kernel(const float* __restrict__ x,
           const float* __restrict__ b1,
           const float* __restrict__ b2,
           const float* __restrict__ b3,
           float* __restrict__ out, int n)
{
    extern __shared__ char sm[];
    const uint32_t sb    = smem_to_u32(sm);
    const uint32_t actHi = sb + ACT_HI_OFF;
    const uint32_t actLo = sb + ACT_LO_OFF;

    const int tid  = threadIdx.x;
    const int warp = tid >> 5;
    const int lane = tid & 31;
    const int g    = lane >> 2;
    const int t    = lane & 3;
    const int m0   = blockIdx.x * 64;

    // ---- input fill: act[feat][node] = split(concat(x, mean)) --------------
    {
        int r = tid >> 2;           // local node 0..63
        int q = tid & 3;            // feature quarter
        int m = m0 + r;
        bool valid = (m < n);
        const float4* xr = (const float4*)(x + (size_t)(valid ? m : 0) * D_NODE);
        const float4* gr = (const float4*)(g_mean + (size_t)(valid ? m : 0) * D_EDGE);
        #pragma unroll
        for (int j = 0; j < 16; j++) {
            int fb = q * 64 + j * 4;
            float4 v = make_float4(0.f, 0.f, 0.f, 0.f);
            if (valid) {
                if (q < 2) v = __ldg(xr + q * 16 + j);
                else       v = __ldg(gr + (q - 2) * 16 + j);
            }
            float vals[4] = {v.x, v.y, v.z, v.w};
            #pragma unroll
            for (int e = 0; e < 4; e++) {
                __nv_bfloat16 hi = __float2bfloat16(vals[e]);
                __nv_bfloat16 lo = __float2bfloat16(vals[e] - __bfloat162float(hi));
                size_t o = (size_t)(fb + e) * 144 + (size_t)r * 2;
                *(__nv_bfloat16*)(sm + ACT_HI_OFF + o) = hi;
                *(__nv_bfloat16*)(sm + ACT_LO_OFF + o) = lo;
            }
        }
    }
    __syncthreads();

    float acc[2][8][4];

    // ---- Layers 1 & 2 (K=256, N=256) ---------------------------------------
    #pragma unroll 1
    for (int L = 0; L < 2; L++) {
        const uint4* wf = g_wfrag + (L == 0 ? 0 : WF_L2_B32 / 4);
        #pragma unroll
        for (int i = 0; i < 2; i++)
            #pragma unroll
            for (int mt = 0; mt < 8; mt++)
                #pragma unroll
                for (int q = 0; q < 4; q++) acc[i][mt][q] = 0.f;

        #pragma unroll
        for (int kc = 0; kc < 4; kc++)
            compute_chunk<2>(acc, wf, warp * 2, 16, kc, actHi, actLo, lane);

        __syncthreads();

        const float* bias = (L == 0) ? b1 : b2;
        const int nb = warp * 32;
        #pragma unroll
        for (int i = 0; i < 2; i++) {
            int fb = nb + i * 16;
            float bg  = __ldg(bias + fb + g);
            float bg8 = __ldg(bias + fb + g + 8);
            size_t rowG  = (size_t)(fb + g) * 144;
            size_t rowG8 = (size_t)(fb + g + 8) * 144;
            #pragma unroll
            for (int mt = 0; mt < 8; mt++) {
                float v0 = fmaxf(acc[i][mt][0] + bg,  0.f);
                float v1 = fmaxf(acc[i][mt][1] + bg,  0.f);
                float v2 = fmaxf(acc[i][mt][2] + bg8, 0.f);
                float v3 = fmaxf(acc[i][mt][3] + bg8, 0.f);
                uint32_t h01, l01, h23, l23;
                split_pack(v0, v1, h01, l01);
                split_pack(v2, v3, h23, l23);
                size_t mB = (size_t)(mt * 8 + 2 * t) * 2;
                *(uint32_t*)(sm + ACT_HI_OFF + rowG  + mB) = h01;
                *(uint32_t*)(sm + ACT_LO_OFF + rowG  + mB) = l01;
                *(uint32_t*)(sm + ACT_HI_OFF + rowG8 + mB) = h23;
                *(uint32_t*)(sm + ACT_LO_OFF + rowG8 + mB) = l23;
            }
        }
        __syncthreads();
    }

    // ---- Layer 3 (K=256, N=128) ---------------------------------------------
    #pragma unroll
    for (int mt = 0; mt < 8; mt++)
        #pragma unroll
        for (int q = 0; q < 4; q++) acc[0][mt][q] = 0.f;

    #pragma unroll
    for (int kc = 0; kc < 4; kc++)
        compute_chunk<1>(acc, g_wfrag + WF_L3_B32 / 4, warp, 8, kc,
                         actHi, actLo, lane);

    // ---- final epilogue: bias, transpose via f32 scratch, coalesced store ---
    {
        const int nb = warp * 16;
        float bg  = __ldg(b3 + nb + g);
        float bg8 = __ldg(b3 + nb + g + 8);
        __syncthreads();
        #pragma unroll
        for (int mt = 0; mt < 8; mt++) {
            float2 v01 = make_float2(acc[0][mt][0] + bg,  acc[0][mt][1] + bg);
            float2 v23 = make_float2(acc[0][mt][2] + bg8, acc[0][mt][3] + bg8);
            size_t mB = (size_t)(mt * 8 + 2 * t) * 4;
            *(float2*)(sm + (size_t)(nb + g)     * 272 + mB) = v01;
            *(float2*)(sm + (size_t)(nb + g + 8) * 272 + mB) = v23;
        }
        __syncthreads();
        int mloc = tid >> 2, fgrp = tid & 3;
        int m = m0 + mloc;
        if (m < n) {
            const float* scr = (const float*)sm;
            #pragma unroll
            for (int i = 0; i < 8; i++) {
                int f = fgrp * 32 + i * 4;
                float4 v;
                v.x = scr[(f + 0) * 68 + mloc];
                v.y = scr[(f + 1) * 68 + mloc];
                v.z = scr[(f + 2) * 68 + mloc];
                v.w = scr[(f + 3) * 68 + mloc];
                *(float4*)(out + (size_t)m * D_OUT + f) = v;
            }
        }
    }
}

// ---------------------------------------------------------------------------
// kernel_launch
// Inputs: 0=x [N,128] f32, 1=edge_index [2,E] i32, 2=edge_attr [E,128] f32,
//         3=W1 [256,256], 4=b1, 5=W2 [256,256], 6=b2, 7=W3 [256,128], 8=b3.
// ---------------------------------------------------------------------------
extern "C" void kernel_launch(void* const* d_in, const int* in_sizes, int n_in,
                              void* d_out, int out_size) {
    const float* x  = (const float*)d_in[0];
    const int* ei   = (const int*)d_in[1];
    const float* ea = (const float*)d_in[2];
    const float* W1 = (const float*)d_in[3];
    const float* b1 = (const float*)d_in[4];
    const float* W2 = (const float*)d_in[5];
    const float* b2 = (const float*)d_in[6];
    const float* W3 = (const float*)d_in[7];
    const float* b3 = (const float*)d_in[8];
    float* out = (float*)d_out;

    const int n = in_sizes[0] / D_NODE;              // 100000
    const int n_edges = in_sizes[2] / D_EDGE;        // 1600000
    const int* col = ei + n_edges;                   // edge_index[1]

    // 1) CSR build
    zero_cnt_kernel<<<(n + 255) / 256, 256>>>(n);
    count_kernel<<<(n_edges + 255) / 256, 256>>>(col, n_edges);
    prefix_kernel<<<1, SCAN_T>>>(n);
    fill_kernel<<<(n_edges + 255) / 256, 256>>>(col, n_edges);
    // 2) weight prep (fragment-order split) — independent of CSR, overlaps
    prep_kernel<<<(WF_TOTAL_B32 + 255) / 256, 256>>>(W1, W2, W3);
    // 3) gather-mean (one warp per node, saturates HBM)
    gather_kernel<<<(n + 7) / 8, 256>>>((const float4*)ea, n);
    // 4) fused tensor-core MLP
    {
        static int smem_set = 0;
        if (!smem_set) {
            cudaFuncSetAttribute(mlp_kernel,
                                 cudaFuncAttributeMaxDynamicSharedMemorySize,
                                 SMEM_BYTES);
            smem_set = 1;
        }
        int blocks = (n + 63) / 64;                  // 1563
        mlp_kernel<<<blocks, 256, SMEM_BYTES>>>(x, b1, b2, b3, out, n);
    }
}

// round 8
// speedup vs baseline: 1.2726x; 1.1166x over previous
#include <cuda_runtime.h>
#include <cuda_bf16.h>
#include <cstdint>

// ---------------------------------------------------------------------------
// Problem constants
// ---------------------------------------------------------------------------
#define N_NODES 100000
#define N_EDGES 1600000
#define D_NODE  128
#define D_EDGE  128
#define D_IN    256
#define HID     256
#define D_OUT   128

// ---------------------------------------------------------------------------
// Scratch (device globals; allocations are forbidden)
// ---------------------------------------------------------------------------
__device__ __align__(16) float g_sum[(size_t)N_NODES * D_EDGE];
__device__ int g_cnt[N_NODES];

// Weight blob in EXACT mma.sync A-fragment order, bf16 hi/lo terms:
//   b32 index = layerBase + ((kstep*NFT + ft)*2 + term)*128 + lane*4 + reg
#define WF_L2_B32 65536
#define WF_L3_B32 131072
#define WF_TOTAL_B32 163840
__device__ __align__(16) uint4 g_wfrag[WF_TOTAL_B32 / 4];

// ---------------------------------------------------------------------------
// SMEM map: activations only (hi + lo), [256 feat][72 bf16] stride 144 B.
// L3 f32 transpose scratch (128 x 68 f32, stride 272 B) overlays act area.
// ---------------------------------------------------------------------------
#define ACT_HI_OFF 0
#define ACT_LO_OFF 36864
#define SMEM_BYTES 73728

// ---------------------------------------------------------------------------
// PTX helpers (arch-portable, valid at compute_103)
// ---------------------------------------------------------------------------
__device__ __forceinline__ uint32_t smem_to_u32(const void* p) {
    uint32_t a;
    asm("{ .reg .u64 t; cvta.to.shared.u64 t, %1; cvt.u32.u64 %0, t; }"
        : "=r"(a) : "l"(p));
    return a;
}

#define LDMX4T(r, addr) \
    asm volatile("ldmatrix.sync.aligned.m8n8.x4.trans.shared.b16 {%0,%1,%2,%3}, [%4];" \
        : "=r"((r)[0]), "=r"((r)[1]), "=r"((r)[2]), "=r"((r)[3]) : "r"(addr))

#define MMA_BF16(d, a, b0v, b1v) \
    asm volatile("mma.sync.aligned.m16n8k16.row.col.f32.bf16.bf16.f32 " \
        "{%0,%1,%2,%3},{%4,%5,%6,%7},{%8,%9},{%0,%1,%2,%3};" \
        : "+f"((d)[0]), "+f"((d)[1]), "+f"((d)[2]), "+f"((d)[3]) \
        : "r"((a)[0]), "r"((a)[1]), "r"((a)[2]), "r"((a)[3]), \
          "r"(b0v), "r"(b1v))

// fp32 pair -> packed bf16x2 hi + lo (a in low half)
__device__ __forceinline__ void split_pack(float a, float b,
                                           uint32_t& hi, uint32_t& lo) {
    __nv_bfloat16 ah = __float2bfloat16(a);
    __nv_bfloat16 bh = __float2bfloat16(b);
    __nv_bfloat16 al = __float2bfloat16(a - __bfloat162float(ah));
    __nv_bfloat16 bl = __float2bfloat16(b - __bfloat162float(bh));
    hi = ((uint32_t)__bfloat16_as_ushort(bh) << 16) | (uint32_t)__bfloat16_as_ushort(ah);
    lo = ((uint32_t)__bfloat16_as_ushort(bl) << 16) | (uint32_t)__bfloat16_as_ushort(al);
}

// ---------------------------------------------------------------------------
// Kernel 1: zero scratch
// ---------------------------------------------------------------------------
__global__ void zero_kernel() {
    int i = blockIdx.x * blockDim.x + threadIdx.x;
    const int total = N_NODES * D_EDGE;
    if (i < total) g_sum[i] = 0.0f;
    if (i < N_NODES) g_cnt[i] = 0;
}

// ---------------------------------------------------------------------------
// Kernel 2: weight prep — bf16 hi/lo fragments in mma A-operand order
// ---------------------------------------------------------------------------
__global__ void prep_kernel(const float* __restrict__ W1,
                            const float* __restrict__ W2,
                            const float* __restrict__ W3) {
    int i = blockIdx.x * blockDim.x + threadIdx.x;
    if (i >= WF_TOTAL_B32) return;
    uint32_t* blob = (uint32_t*)g_wfrag;
    const float* W; int idx, Nl, NFT;
    if (i < WF_L2_B32)      { W = W1; idx = i;             Nl = 256; NFT = 16; }
    else if (i < WF_L3_B32) { W = W2; idx = i - WF_L2_B32; Nl = 256; NFT = 16; }
    else                    { W = W3; idx = i - WF_L3_B32; Nl = 128; NFT = 8;  }
    int reg   = idx & 3;
    int lane  = (idx >> 2) & 31;
    int term  = (idx >> 7) & 1;
    int ft    = (idx >> 8) % NFT;
    int kstep = (idx >> 8) / NFT;
    int r = lane >> 2, t = lane & 3;
    int m = ft * 16 + r + (reg & 1) * 8;
    int k = kstep * 16 + t * 2 + (reg >> 1) * 8;
    float w0 = __ldg(W + (size_t)k * Nl + m);
    float w1 = __ldg(W + (size_t)(k + 1) * Nl + m);
    uint32_t hi, lo;
    split_pack(w0, w1, hi, lo);
    blob[i] = term ? lo : hi;
}

// ---------------------------------------------------------------------------
// Kernel 3: scatter-add (red.v4, streaming reads) + degree count.
// One warp per edge row — edge_attr reads perfectly coalesced & sequential.
// ---------------------------------------------------------------------------
__global__ void __launch_bounds__(256)
scatter_kernel(const int* __restrict__ col,
               const float4* __restrict__ edge_attr,
               int n_edges) {
    long long gid = (long long)blockIdx.x * blockDim.x + threadIdx.x;
    if (gid >= (long long)n_edges * 32) return;
    int e = (int)(gid >> 5);
    int c = (int)(gid & 31);
    int dst = __ldg(col + e);
    if (c == 0) atomicAdd(&g_cnt[dst], 1);
    float4 v = __ldg(edge_attr + (size_t)e * 32 + c);
    float* p = g_sum + (size_t)dst * D_EDGE + c * 4;
    asm volatile("red.global.add.v4.f32 [%0], {%1,%2,%3,%4};"
                 :: "l"(p), "f"(v.x), "f"(v.y), "f"(v.z), "f"(v.w)
                 : "memory");
}

// ---------------------------------------------------------------------------
// Software-pipelined layer MMA: 16 k-steps, A-fragment register double-buffer.
// k-step i+1's LDGs issue before k-step i's ldmatrix+MMA block executes.
// ---------------------------------------------------------------------------
template<int NT>
__device__ __forceinline__ void layer_mma(
    float acc[2][8][4],
    const uint4* __restrict__ wf,    // layer base (uint4 units)
    int ftBase, int NFT,
    uint32_t actHi, uint32_t actLo, int lane)
{
    const uint32_t bK  = (uint32_t)(lane & 15);
    const uint32_t bMH = (uint32_t)((lane >> 4) * 8);

    uint4 curH[NT], curL[NT], nxtH[NT], nxtL[NT];
    #pragma unroll
    for (int i = 0; i < NT; i++) {
        const uint4* p = wf + (size_t)((ftBase + i) * 2) * 32 + lane;
        curH[i] = __ldg(p);
        curL[i] = __ldg(p + 32);
    }

    #pragma unroll
    for (int kstep = 0; kstep < 16; kstep++) {
        // prefetch next k-step's A fragments (hidden behind this step's MMAs)
        if (kstep < 15) {
            #pragma unroll
            for (int i = 0; i < NT; i++) {
                const uint4* p = wf
                    + (size_t)(((kstep + 1) * NFT + ftBase + i) * 2) * 32 + lane;
                nxtH[i] = __ldg(p);
                nxtL[i] = __ldg(p + 32);
            }
        }
        const uint32_t kByte = (uint32_t)(kstep * 16 + (int)bK) * 144u;
        #pragma unroll
        for (int mt = 0; mt < 4; mt++) {
            const uint32_t mByte = (uint32_t)(mt * 16 + (int)bMH) * 2u;
            uint32_t bh[4], bl[4];
            LDMX4T(bh, actHi + kByte + mByte);
            LDMX4T(bl, actLo + kByte + mByte);
            #pragma unroll
            for (int i = 0; i < NT; i++) {
                uint32_t ah[4] = {curH[i].x, curH[i].y, curH[i].z, curH[i].w};
                uint32_t al[4] = {curL[i].x, curL[i].y, curL[i].z, curL[i].w};
                #pragma unroll
                for (int h = 0; h < 2; h++) {
                    MMA_BF16(acc[i][mt * 2 + h], ah, bh[2 * h], bh[2 * h + 1]);
                    MMA_BF16(acc[i][mt * 2 + h], ah, bl[2 * h], bl[2 * h + 1]);
                    MMA_BF16(acc[i][mt * 2 + h], al, bh[2 * h], bh[2 * h + 1]);
                }
            }
        }
        #pragma unroll
        for (int i = 0; i < NT; i++) {   // register rename under full unroll
            curH[i] = nxtH[i];
            curL[i] = nxtL[i];
        }
    }
}

// ---------------------------------------------------------------------------
// Kernel 4: fused 3-layer MLP. CTA = 64 nodes, 256 threads, 2 CTAs/SM.
// ---------------------------------------------------------------------------
__global__ void __launch_bounds__(256, 2)
mlp_kernel(const float* __restrict__ x,
           const float* __restrict__ b1,
           const float* __restrict__ b2,
           const float* __restrict__ b3,
           float* __restrict__ out, int n)
{
    extern __shared__ char sm[];
    const uint32_t sb    = smem_to_u32(sm);
    const uint32_t actHi = sb + ACT_HI_OFF;
    const uint32_t actLo = sb + ACT_LO_OFF;

    const int tid  = threadIdx.x;
    const int warp = tid >> 5;
    const int lane = tid & 31;
    const int g    = lane >> 2;
    const int t    = lane & 3;
    const int m0   = blockIdx.x * 64;

    // ---- input fill: act[feat][node] = split(concat(x, mean)) --------------
    {
        int r = tid >> 2;           // local node 0..63
        int q = tid & 3;            // feature quarter
        int m = m0 + r;
        bool valid = (m < n);
        float inv = 1.0f;
        if (valid) inv = 1.0f / fmaxf((float)__ldg(&g_cnt[m]), 1.0f);
        const float4* xr = (const float4*)(x + (size_t)(valid ? m : 0) * D_NODE);
        const float4* gr = (const float4*)(g_sum + (size_t)(valid ? m : 0) * D_EDGE);
        #pragma unroll
        for (int j = 0; j < 16; j++) {
            int fb = q * 64 + j * 4;
            float4 v = make_float4(0.f, 0.f, 0.f, 0.f);
            if (valid) {
                if (q < 2) v = __ldg(xr + q * 16 + j);
                else {
                    v = __ldg(gr + (q - 2) * 16 + j);
                    v.x *= inv; v.y *= inv; v.z *= inv; v.w *= inv;
                }
            }
            float vals[4] = {v.x, v.y, v.z, v.w};
            #pragma unroll
            for (int e = 0; e < 4; e++) {
                __nv_bfloat16 hi = __float2bfloat16(vals[e]);
                __nv_bfloat16 lo = __float2bfloat16(vals[e] - __bfloat162float(hi));
                size_t o = (size_t)(fb + e) * 144 + (size_t)r * 2;
                *(__nv_bfloat16*)(sm + ACT_HI_OFF + o) = hi;
                *(__nv_bfloat16*)(sm + ACT_LO_OFF + o) = lo;
            }
        }
    }
    __syncthreads();

    float acc[2][8][4];

    // ---- Layers 1 & 2 (K=256, N=256) ---------------------------------------
    #pragma unroll 1
    for (int L = 0; L < 2; L++) {
        const uint4* wf = g_wfrag + (L == 0 ? 0 : WF_L2_B32 / 4);
        #pragma unroll
        for (int i = 0; i < 2; i++)
            #pragma unroll
            for (int mt = 0; mt < 8; mt++)
                #pragma unroll
                for (int q = 0; q < 4; q++) acc[i][mt][q] = 0.f;

        layer_mma<2>(acc, wf, warp * 2, 16, actHi, actLo, lane);

        __syncthreads();     // all warps done READING act for this layer

        const float* bias = (L == 0) ? b1 : b2;
        const int nb = warp * 32;
        #pragma unroll
        for (int i = 0; i < 2; i++) {
            int fb = nb + i * 16;
            float bg  = __ldg(bias + fb + g);
            float bg8 = __ldg(bias + fb + g + 8);
            size_t rowG  = (size_t)(fb + g) * 144;
            size_t rowG8 = (size_t)(fb + g + 8) * 144;
            #pragma unroll
            for (int mt = 0; mt < 8; mt++) {
                float v0 = fmaxf(acc[i][mt][0] + bg,  0.f);
                float v1 = fmaxf(acc[i][mt][1] + bg,  0.f);
                float v2 = fmaxf(acc[i][mt][2] + bg8, 0.f);
                float v3 = fmaxf(acc[i][mt][3] + bg8, 0.f);
                uint32_t h01, l01, h23, l23;
                split_pack(v0, v1, h01, l01);
                split_pack(v2, v3, h23, l23);
                size_t mB = (size_t)(mt * 8 + 2 * t) * 2;
                *(uint32_t*)(sm + ACT_HI_OFF + rowG  + mB) = h01;
                *(uint32_t*)(sm + ACT_LO_OFF + rowG  + mB) = l01;
                *(uint32_t*)(sm + ACT_HI_OFF + rowG8 + mB) = h23;
                *(uint32_t*)(sm + ACT_LO_OFF + rowG8 + mB) = l23;
            }
        }
        __syncthreads();     // writes visible before next layer reads
    }

    // ---- Layer 3 (K=256, N=128) ---------------------------------------------
    #pragma unroll
    for (int mt = 0; mt < 8; mt++)
        #pragma unroll
        for (int q = 0; q < 4; q++) acc[0][mt][q] = 0.f;

    layer_mma<1>(acc, g_wfrag + WF_L3_B32 / 4, warp, 8, actHi, actLo, lane);

    // ---- final epilogue: bias, transpose via f32 scratch, coalesced store ---
    {
        const int nb = warp * 16;
        float bg  = __ldg(b3 + nb + g);
        float bg8 = __ldg(b3 + nb + g + 8);
        __syncthreads();     // all done reading act (scratch overlays it)
        #pragma unroll
        for (int mt = 0; mt < 8; mt++) {
            float2 v01 = make_float2(acc[0][mt][0] + bg,  acc[0][mt][1] + bg);
            float2 v23 = make_float2(acc[0][mt][2] + bg8, acc[0][mt][3] + bg8);
            size_t mB = (size_t)(mt * 8 + 2 * t) * 4;
            *(float2*)(sm + (size_t)(nb + g)     * 272 + mB) = v01;
            *(float2*)(sm + (size_t)(nb + g + 8) * 272 + mB) = v23;
        }
        __syncthreads();
        int mloc = tid >> 2, fgrp = tid & 3;
        int m = m0 + mloc;
        if (m < n) {
            const float* scr = (const float*)sm;
            #pragma unroll
            for (int i = 0; i < 8; i++) {
                int f = fgrp * 32 + i * 4;
                float4 v;
                v.x = scr[(f + 0) * 68 + mloc];
                v.y = scr[(f + 1) * 68 + mloc];
                v.z = scr[(f + 2) * 68 + mloc];
                v.w = scr[(f + 3) * 68 + mloc];
                *(float4*)(out + (size_t)m * D_OUT + f) = v;
            }
        }
    }
}

// ---------------------------------------------------------------------------
// kernel_launch
// Inputs: 0=x [N,128] f32, 1=edge_index [2,E] i32, 2=edge_attr [E,128] f32,
//         3=W1 [256,256], 4=b1, 5=W2 [256,256], 6=b2, 7=W3 [256,128], 8=b3.
// ---------------------------------------------------------------------------
extern "C" void kernel_launch(void* const* d_in, const int* in_sizes, int n_in,
                              void* d_out, int out_size) {
    const float* x  = (const float*)d_in[0];
    const int* ei   = (const int*)d_in[1];
    const float* ea = (const float*)d_in[2];
    const float* W1 = (const float*)d_in[3];
    const float* b1 = (const float*)d_in[4];
    const float* W2 = (const float*)d_in[5];
    const float* b2 = (const float*)d_in[6];
    const float* W3 = (const float*)d_in[7];
    const float* b3 = (const float*)d_in[8];
    float* out = (float*)d_out;

    const int n = in_sizes[0] / D_NODE;              // 100000
    const int n_edges = in_sizes[2] / D_EDGE;        // 1600000
    const int* col = ei + n_edges;                   // edge_index[1]

    // 1) zero scratch
    {
        int total = N_NODES * D_EDGE;
        zero_kernel<<<(total + 255) / 256, 256>>>();
    }
    // 2) weight prep (fragment-order split)
    prep_kernel<<<(WF_TOTAL_B32 + 255) / 256, 256>>>(W1, W2, W3);
    // 3) scatter-add + counts (streaming reads, red.v4 atomics)
    {
        long long threads = (long long)n_edges * 32;
        int blocks = (int)((threads + 255) / 256);
        scatter_kernel<<<blocks, 256>>>(col, (const float4*)ea, n_edges);
    }
    // 4) fused tensor-core MLP
    {
        static int smem_set = 0;
        if (!smem_set) {
            cudaFuncSetAttribute(mlp_kernel,
                                 cudaFuncAttributeMaxDynamicSharedMemorySize,
                                 SMEM_BYTES);
            smem_set = 1;
        }
        int blocks = (n + 63) / 64;                  // 1563
        mlp_kernel<<<blocks, 256, SMEM_BYTES>>>(x, b1, b2, b3, out, n);
    }
}